// round 9
// baseline (speedup 1.0000x reference)
#include <cuda_runtime.h>
#include <cuda_fp16.h>
#include <cstdint>
#include <math.h>

// ---------------------------------------------------------------------------
// Problem constants
// ---------------------------------------------------------------------------
#define BB     8
#define NHID   256
#define LL     2048
#define DD     512            // q/k/v channels
#define DOUT   2048
#define MM     (BB*LL)        // 16384
#define NQKV   1536           // q|k|v fused N
#define K1     256            // QKV GEMM K
#define K2     512            // WO GEMM K

// GEMM tiling (SM80-style, base-target mma.sync fp16)
// 512 threads = 16 warps as 4(M) x 4(N); warp tile 32x64.
#define BM     128
#define BN     256
#define BK     64
#define TH     512
#define STAGES 4
#define STAGE_A (BM*BK*2)          // 16 KB
#define STAGE_B (BN*BK*2)          // 32 KB
#define STAGE_SZ (STAGE_A+STAGE_B) // 48 KB
#define SMEM_SZ (STAGES*STAGE_SZ)  // 192 KB

#define GRID1  148                 // persistent qkv grid (1 CTA/SM)
#define NT1    (NQKV/BN)           // 6  n-tiles
#define MT1    (MM/BM)             // 128 m-tiles
#define NTILES1 (NT1*MT1)          // 768
#define KT1    (K1/BK)             // 4

// ---------------------------------------------------------------------------
// Scratch (device globals — sanctioned no-alloc path)
// ---------------------------------------------------------------------------
__device__ __half g_A1[(size_t)MM * K1];     // x^T  [m][k] fp16
__device__ __half g_B1[(size_t)NQKV * K1];   // [Wq|Wk|Wv]^T [n][k] fp16
__device__ __half g_A2[(size_t)MM * K2];     // att  [m][k] fp16
__device__ __half g_B2[(size_t)DOUT * K2];   // Wo^T [n][k] fp16
__device__ __half g_qkv[(size_t)MM * NQKV];  // fp16 q|k|v (bias included)

// ---------------------------------------------------------------------------
// Helpers (all base-target PTX: cp.async, ldmatrix, mma.sync)
// ---------------------------------------------------------------------------
__device__ __forceinline__ uint32_t smem_u32(const void* p) {
    uint32_t a;
    asm("{ .reg .u64 t; cvta.to.shared.u64 t, %1; cvt.u32.u64 %0, t; }"
        : "=r"(a) : "l"(p));
    return a;
}

#define SWZ(x) ((x) ^ ((((x) >> 7) & 7) << 4))   // Swizzle<3,4,3>, 128B rows

#define CPASYNC16(dst, src) \
    asm volatile("cp.async.cg.shared.global [%0], [%1], 16;" \
                 :: "r"(dst), "l"(src))
#define CPCOMMIT() asm volatile("cp.async.commit_group;" ::: "memory")
#define CPWAIT(n)  asm volatile("cp.async.wait_group %0;" :: "n"(n) : "memory")

__device__ __forceinline__ void ldsm4(uint32_t& r0, uint32_t& r1,
                                      uint32_t& r2, uint32_t& r3, uint32_t a) {
    asm volatile("ldmatrix.sync.aligned.m8n8.x4.shared.b16 {%0,%1,%2,%3}, [%4];"
                 : "=r"(r0), "=r"(r1), "=r"(r2), "=r"(r3) : "r"(a));
}

__device__ __forceinline__ void mma16816(float* d, const uint32_t* a,
                                         const uint32_t* b) {
    asm volatile(
        "mma.sync.aligned.m16n8k16.row.col.f32.f16.f16.f32 "
        "{%0,%1,%2,%3}, {%4,%5,%6,%7}, {%8,%9}, {%0,%1,%2,%3};"
        : "+f"(d[0]), "+f"(d[1]), "+f"(d[2]), "+f"(d[3])
        : "r"(a[0]), "r"(a[1]), "r"(a[2]), "r"(a[3]), "r"(b[0]), "r"(b[1]));
}

// ---------------------------------------------------------------------------
// QKV GEMM (PERSISTENT): g_qkv[m][n] = fp16( A1[m].B1[n] + bias[n] )
// 148 CTAs; each streams its tile list through ONE continuous cp.async
// pipeline. Epilogue is register->gmem only (never touches staged smem).
// ---------------------------------------------------------------------------
__device__ __forceinline__ float qkv_bias(int n, const float* __restrict__ bq,
                                          const float* __restrict__ bk,
                                          const float* __restrict__ bv) {
    if (n < DD)     return bq[n];
    if (n < 2 * DD) return bk[n - DD];
    return bv[n - 2 * DD];
}

__global__ __launch_bounds__(TH, 1)
void qkv_gemm(const float* __restrict__ bq, const float* __restrict__ bk,
              const float* __restrict__ bv) {
    extern __shared__ __align__(1024) char smem[];
    const int bid  = blockIdx.x;
    const int tid  = threadIdx.x;
    const int wid  = tid >> 5;
    const int lane = tid & 31;
    const int wmo  = (wid & 3) * 32;
    const int wno  = (wid >> 2) * 64;
    const uint32_t sb = smem_u32(smem);

    const int ntile = (NTILES1 - bid + GRID1 - 1) / GRID1;  // 5 or 6
    const int total = ntile * KT1;

    auto load_chunk = [&](int idx, int s) {
        const int t  = bid + (idx >> 2) * GRID1;   // KT1 == 4
        const int kt = idx & 3;
        const int n0 = (t % NT1) * BN;
        const int m0 = (t / NT1) * BM;
        const uint32_t as = sb + s * STAGE_SZ;
        const uint32_t bs = as + STAGE_A;
        const __half* Asrc = g_A1 + (size_t)m0 * K1 + kt * BK;
        const __half* Bsrc = g_B1 + (size_t)n0 * K1 + kt * BK;
#pragma unroll
        for (int i = 0; i < 2; ++i) {              // A: 1024 16B-chunks
            const int x2 = tid + i * TH;
            const int r = x2 >> 3, c = x2 & 7;
            CPASYNC16(as + SWZ(r * 128 + c * 16), Asrc + (size_t)r * K1 + c * 8);
        }
#pragma unroll
        for (int i = 0; i < 4; ++i) {              // B: 2048 16B-chunks
            const int x2 = tid + i * TH;
            const int r = x2 >> 3, c = x2 & 7;
            CPASYNC16(bs + SWZ(r * 128 + c * 16), Bsrc + (size_t)r * K1 + c * 8);
        }
    };

    float acc[2][8][4];
#pragma unroll
    for (int i = 0; i < 2; ++i)
#pragma unroll
        for (int j = 0; j < 8; ++j)
#pragma unroll
            for (int r = 0; r < 4; ++r) acc[i][j][r] = 0.f;

    int fetch = 0;
    for (; fetch < STAGES - 1 && fetch < total; ++fetch) {
        load_chunk(fetch, fetch % STAGES); CPCOMMIT();
    }
    CPWAIT(STAGES - 2);
    __syncthreads();

    const int aRow = wmo + (lane & 15);
    const int aCol = (lane >> 4) << 4;
    const int bRow = wno + ((lane >> 4) << 3) + (lane & 7);
    const int bCol = ((lane >> 3) & 1) << 4;

    for (int ci = 0; ci < total; ++ci) {
        const uint32_t as = sb + (ci % STAGES) * STAGE_SZ;
        const uint32_t bs = as + STAGE_A;
#pragma unroll
        for (int ks = 0; ks < 4; ++ks) {
            uint32_t af[2][4], bf[4][4];
#pragma unroll
            for (int mi = 0; mi < 2; ++mi) {
                const uint32_t a = as + SWZ((aRow + mi * 16) * 128 + ks * 32 + aCol);
                ldsm4(af[mi][0], af[mi][1], af[mi][2], af[mi][3], a);
            }
#pragma unroll
            for (int ni = 0; ni < 4; ++ni) {
                const uint32_t a = bs + SWZ((bRow + ni * 16) * 128 + ks * 32 + bCol);
                ldsm4(bf[ni][0], bf[ni][1], bf[ni][2], bf[ni][3], a);
            }
#pragma unroll
            for (int mi = 0; mi < 2; ++mi)
#pragma unroll
                for (int ni = 0; ni < 4; ++ni) {
                    mma16816(acc[mi][ni * 2],     af[mi], &bf[ni][0]);
                    mma16816(acc[mi][ni * 2 + 1], af[mi], &bf[ni][2]);
                }
        }
        if (fetch < total) { load_chunk(fetch, fetch % STAGES); ++fetch; }
        CPCOMMIT();
        CPWAIT(STAGES - 2);
        __syncthreads();

        if ((ci & 3) == 3) {
            // Tile finished: epilogue straight from registers (no smem).
            const int t  = bid + (ci >> 2) * GRID1;
            const int n0 = (t % NT1) * BN;
            const int m0 = (t / NT1) * BM;
            const int wm = m0 + wmo;
            const int wn = n0 + wno;
#pragma unroll
            for (int mi = 0; mi < 2; ++mi) {
                const int r0 = wm + mi * 16 + (lane >> 2);
#pragma unroll
                for (int ni = 0; ni < 8; ++ni) {
                    const int n = wn + ni * 8 + 2 * (lane & 3);
                    const float b0 = qkv_bias(n, bq, bk, bv);
                    const float b1 = qkv_bias(n + 1, bq, bk, bv);
                    const __half2 v0 = __floats2half2_rn(acc[mi][ni][0] + b0, acc[mi][ni][1] + b1);
                    const __half2 v1 = __floats2half2_rn(acc[mi][ni][2] + b0, acc[mi][ni][3] + b1);
                    *reinterpret_cast<__half2*>(&g_qkv[(size_t)r0 * NQKV + n])       = v0;
                    *reinterpret_cast<__half2*>(&g_qkv[(size_t)(r0 + 8) * NQKV + n]) = v1;
#pragma unroll
                    for (int r = 0; r < 4; ++r) acc[mi][ni][r] = 0.f;
                }
            }
        }
    }
}

// ---------------------------------------------------------------------------
// WO GEMM (unchanged R7 structure): out[b][n][l] = A2[m].B2[n] + bo[n]
// ---------------------------------------------------------------------------
template <int KTOT>
__device__ __forceinline__ void gemm_mainloop(const __half* __restrict__ Ag,
                                              const __half* __restrict__ Bg,
                                              char* smem, float (&acc)[2][8][4])
{
    const int tid  = threadIdx.x;
    const int wid  = tid >> 5;
    const int lane = tid & 31;
    const int wm   = (wid & 3) * 32;
    const int wn   = (wid >> 2) * 64;
    const uint32_t sb = smem_u32(smem);
    const int KT = KTOT / BK;

    auto load_stage = [&](int kt, int s) {
        const uint32_t as = sb + s * STAGE_SZ;
        const uint32_t bs = as + STAGE_A;
        const __half* Asrc = Ag + kt * BK;
        const __half* Bsrc = Bg + kt * BK;
#pragma unroll
        for (int i = 0; i < 2; ++i) {
            const int idx = tid + i * TH;
            const int r = idx >> 3, c = idx & 7;
            CPASYNC16(as + SWZ(r * 128 + c * 16), Asrc + (size_t)r * KTOT + c * 8);
        }
#pragma unroll
        for (int i = 0; i < 4; ++i) {
            const int idx = tid + i * TH;
            const int r = idx >> 3, c = idx & 7;
            CPASYNC16(bs + SWZ(r * 128 + c * 16), Bsrc + (size_t)r * KTOT + c * 8);
        }
    };

    int fetch = 0;
    for (; fetch < STAGES - 1 && fetch < KT; ++fetch) { load_stage(fetch, fetch); CPCOMMIT(); }
    CPWAIT(STAGES - 2);
    __syncthreads();

    const int aRow = wm + (lane & 15);
    const int aCol = (lane >> 4) << 4;
    const int bRow = wn + ((lane >> 4) << 3) + (lane & 7);
    const int bCol = ((lane >> 3) & 1) << 4;

    for (int kt = 0; kt < KT; ++kt) {
        const uint32_t as = sb + (kt % STAGES) * STAGE_SZ;
        const uint32_t bs = as + STAGE_A;
#pragma unroll
        for (int ks = 0; ks < 4; ++ks) {
            uint32_t af[2][4], bf[4][4];
#pragma unroll
            for (int mi = 0; mi < 2; ++mi) {
                const uint32_t a = as + SWZ((aRow + mi * 16) * 128 + ks * 32 + aCol);
                ldsm4(af[mi][0], af[mi][1], af[mi][2], af[mi][3], a);
            }
#pragma unroll
            for (int ni = 0; ni < 4; ++ni) {
                const uint32_t a = bs + SWZ((bRow + ni * 16) * 128 + ks * 32 + bCol);
                ldsm4(bf[ni][0], bf[ni][1], bf[ni][2], bf[ni][3], a);
            }
#pragma unroll
            for (int mi = 0; mi < 2; ++mi)
#pragma unroll
                for (int ni = 0; ni < 4; ++ni) {
                    mma16816(acc[mi][ni * 2],     af[mi], &bf[ni][0]);
                    mma16816(acc[mi][ni * 2 + 1], af[mi], &bf[ni][2]);
                }
        }
        if (fetch < KT) { load_stage(fetch, fetch % STAGES); ++fetch; }
        CPCOMMIT();
        CPWAIT(STAGES - 2);
        __syncthreads();
    }
}

#define CSTR 132
__global__ __launch_bounds__(TH, 1)
void wo_gemm(const float* __restrict__ bo, float* __restrict__ out) {
    extern __shared__ __align__(1024) char smem[];
    const int n0 = blockIdx.x * BN;
    const int m0 = blockIdx.y * BM;
    const int b  = m0 / LL;
    const int l0 = m0 % LL;

    float acc[2][8][4];
#pragma unroll
    for (int i = 0; i < 2; ++i)
#pragma unroll
        for (int j = 0; j < 8; ++j)
#pragma unroll
            for (int r = 0; r < 4; ++r) acc[i][j][r] = 0.f;

    gemm_mainloop<K2>(g_A2 + (size_t)m0 * K2, g_B2 + (size_t)n0 * K2, smem, acc);

    float* Cs = reinterpret_cast<float*>(smem);
    const int wid = threadIdx.x >> 5, lane = threadIdx.x & 31;
    const int wm = (wid & 3) * 32;
    const int wn = (wid >> 2) * 64;
#pragma unroll
    for (int mi = 0; mi < 2; ++mi) {
        const int m = wm + mi * 16 + (lane >> 2);
#pragma unroll
        for (int ni = 0; ni < 8; ++ni) {
            const int n = wn + ni * 8 + 2 * (lane & 3);
            Cs[(size_t)n * CSTR + m]           = acc[mi][ni][0];
            Cs[(size_t)(n + 1) * CSTR + m]     = acc[mi][ni][1];
            Cs[(size_t)n * CSTR + m + 8]       = acc[mi][ni][2];
            Cs[(size_t)(n + 1) * CSTR + m + 8] = acc[mi][ni][3];
        }
    }
    __syncthreads();

    float* outb = out + (size_t)b * DOUT * LL;
    for (int i = threadIdx.x; i < BN * (BM / 4); i += TH) {
        const int n = i >> 5;
        const int c = (i & 31) * 4;
        const float bv = bo[n0 + n];
        float4 v;
        v.x = Cs[(size_t)n * CSTR + c + 0] + bv;
        v.y = Cs[(size_t)n * CSTR + c + 1] + bv;
        v.z = Cs[(size_t)n * CSTR + c + 2] + bv;
        v.w = Cs[(size_t)n * CSTR + c + 3] + bv;
        *reinterpret_cast<float4*>(outb + (size_t)(n0 + n) * LL + l0 + c) = v;
    }
}

// ---------------------------------------------------------------------------
// Conversions (fp32 -> fp16, with transposes)
// ---------------------------------------------------------------------------
__global__ __launch_bounds__(1024)
void conv_x_kernel(const float* __restrict__ x) {
    __shared__ float t[32][33];
    const int b  = blockIdx.z;
    const int c0 = blockIdx.y * 32, l0 = blockIdx.x * 32;
    const int tx = threadIdx.x, ty = threadIdx.y;
    t[ty][tx] = x[((size_t)(b * NHID + c0 + ty)) * LL + l0 + tx];
    __syncthreads();
    g_A1[(size_t)(b * LL + l0 + ty) * K1 + c0 + tx] = __float2half(t[tx][ty]);
}

__global__ __launch_bounds__(1024)
void conv_w_all(const float* __restrict__ Wq, const float* __restrict__ Wk,
                const float* __restrict__ Wv, const float* __restrict__ Wo) {
    __shared__ float t[32][33];
    const int bid = blockIdx.x;
    const float* W;
    __half* dst;
    int N, roff, dstride, lb, ntiles;
    if (bid < 384) {
        const int sel = bid >> 7;
        lb = bid & 127;
        W = (sel == 0) ? Wq : (sel == 1) ? Wk : Wv;
        dst = g_B1; N = DD; roff = sel * DD; dstride = K1; ntiles = DD / 32;
    } else {
        lb = bid - 384;
        W = Wo; dst = g_B2; N = DOUT; roff = 0; dstride = K2; ntiles = DOUT / 32;
    }
    const int n0 = (lb % ntiles) * 32;
    const int k0 = (lb / ntiles) * 32;
    const int tx = threadIdx.x, ty = threadIdx.y;
    t[ty][tx] = W[(size_t)(k0 + ty) * N + n0 + tx];
    __syncthreads();
    dst[(size_t)(roff + n0 + ty) * dstride + k0 + tx] = __float2half(t[tx][ty]);
}

// No-op spacer (slot alignment: capture slot is my launch index 3).
__global__ void spacer_kernel() {}

// ---------------------------------------------------------------------------
// Window-3 attention (fp16 qkv in, fp16 att out)
// ---------------------------------------------------------------------------
__global__ __launch_bounds__(256)
void attn_win3() {
    const int tid = threadIdx.x;
    const int m   = blockIdx.x * 2 + (tid >> 7);
    const int t   = tid & 127;
    const int h   = t >> 4;
    const int g   = t & 15;
    const int l   = m & (LL - 1);

    const size_t rowb = (size_t)m * NQKV;
    const int    co   = h * 64 + g * 4;

    const uint2 qraw = *reinterpret_cast<const uint2*>(g_qkv + rowb + co);
    const float2 qa = __half22float2(*reinterpret_cast<const __half2*>(&qraw.x));
    const float2 qb = __half22float2(*reinterpret_cast<const __half2*>(&qraw.y));

    float  s[3];
    float2 va[3], vb[3];
#pragma unroll
    for (int w = 0; w < 3; ++w) {
        const int lw = l + w - 1;
        float2 ka = make_float2(0.f, 0.f), kb = make_float2(0.f, 0.f);
        va[w] = make_float2(0.f, 0.f);
        vb[w] = make_float2(0.f, 0.f);
        if (lw >= 0 && lw < LL) {
            const size_t rb = rowb + (size_t)(w - 1) * NQKV;
            const uint2 kr = *reinterpret_cast<const uint2*>(g_qkv + rb + DD + co);
            const uint2 vr = *reinterpret_cast<const uint2*>(g_qkv + rb + 2 * DD + co);
            ka = __half22float2(*reinterpret_cast<const __half2*>(&kr.x));
            kb = __half22float2(*reinterpret_cast<const __half2*>(&kr.y));
            va[w] = __half22float2(*reinterpret_cast<const __half2*>(&vr.x));
            vb[w] = __half22float2(*reinterpret_cast<const __half2*>(&vr.y));
        }
        float p = qa.x * ka.x + qa.y * ka.y + qb.x * kb.x + qb.y * kb.y;
        p += __shfl_xor_sync(0xffffffffu, p, 8);
        p += __shfl_xor_sync(0xffffffffu, p, 4);
        p += __shfl_xor_sync(0xffffffffu, p, 2);
        p += __shfl_xor_sync(0xffffffffu, p, 1);
        s[w] = p * 0.125f;   // 1/sqrt(64)
    }

    const float mx = fmaxf(s[0], fmaxf(s[1], s[2]));
    const float e0 = expf(s[0] - mx), e1 = expf(s[1] - mx), e2 = expf(s[2] - mx);
    const float inv = 1.f / (e0 + e1 + e2);

    __half o[4];
    o[0] = __float2half((e0 * va[0].x + e1 * va[1].x + e2 * va[2].x) * inv);
    o[1] = __float2half((e0 * va[0].y + e1 * va[1].y + e2 * va[2].y) * inv);
    o[2] = __float2half((e0 * vb[0].x + e1 * vb[1].x + e2 * vb[2].x) * inv);
    o[3] = __float2half((e0 * vb[0].y + e1 * vb[1].y + e2 * vb[2].y) * inv);

    *reinterpret_cast<uint2*>(g_A2 + (size_t)m * K2 + co) = *reinterpret_cast<uint2*>(o);
}

// ---------------------------------------------------------------------------
extern "C" void kernel_launch(void* const* d_in, const int* in_sizes, int n_in,
                              void* d_out, int out_size)
{
    const float* x  = (const float*)d_in[0];
    const float* Wq = (const float*)d_in[1];
    const float* bq = (const float*)d_in[2];
    const float* Wk = (const float*)d_in[3];
    const float* bk = (const float*)d_in[4];
    const float* Wv = (const float*)d_in[5];
    const float* bv = (const float*)d_in[6];
    const float* Wo = (const float*)d_in[7];
    const float* bo = (const float*)d_in[8];
    float* out = (float*)d_out;

    cudaFuncSetAttribute(qkv_gemm, cudaFuncAttributeMaxDynamicSharedMemorySize, SMEM_SZ);
    cudaFuncSetAttribute(wo_gemm,  cudaFuncAttributeMaxDynamicSharedMemorySize, SMEM_SZ);

    dim3 blk(32, 32);
    // idx:   0              1           2        3 (capture)   4       5
    conv_x_kernel<<<dim3(LL / 32, NHID / 32, BB), blk>>>(x);
    conv_w_all<<<1408, blk>>>(Wq, Wk, Wv, Wo);
    spacer_kernel<<<1, 32>>>();
    qkv_gemm<<<GRID1, TH, SMEM_SZ>>>(bq, bk, bv);
    attn_win3<<<MM / 2, 256>>>();
    wo_gemm<<<dim3(DOUT / BN, MM / BM), TH, SMEM_SZ>>>(bo, out);
}

// round 11
// speedup vs baseline: 1.1537x; 1.1537x over previous
#include <cuda_runtime.h>
#include <cuda_fp16.h>
#include <cstdint>
#include <math.h>

// ---------------------------------------------------------------------------
// Problem constants
// ---------------------------------------------------------------------------
#define BB     8
#define NHID   256
#define LL     2048
#define DD     512            // q/k/v channels
#define DOUT   2048
#define MM     (BB*LL)        // 16384
#define NQKV   1536           // q|k|v fused N
#define K1     256            // QKV GEMM K
#define K2     512            // WO GEMM K

// GEMM tiling: 256 threads = 8 warps as 4(M) x 2(N); warp tile 32x64.
// 96KB smem/CTA, 2 CTAs per SM.
#define BM     128
#define BN     128
#define BK     64
#define TH     256
#define STAGES 3
#define STAGE_A (BM*BK*2)          // 16 KB
#define STAGE_B (BN*BK*2)          // 16 KB
#define STAGE_SZ (STAGE_A+STAGE_B) // 32 KB
#define SMEM_SZ (STAGES*STAGE_SZ)  // 96 KB

// ---------------------------------------------------------------------------
// Scratch (device globals — sanctioned no-alloc path)
// ---------------------------------------------------------------------------
__device__ __half g_A1[(size_t)MM * K1];     // x^T  [m][k] fp16
__device__ __half g_B1[(size_t)NQKV * K1];   // [Wq|Wk|Wv]^T [n][k] fp16
__device__ __half g_A2[(size_t)MM * K2];     // att  [m][k] fp16
__device__ __half g_B2[(size_t)DOUT * K2];   // Wo^T [n][k] fp16
__device__ __half g_qkv[(size_t)MM * NQKV];  // fp16 q|k|v (bias included)

// ---------------------------------------------------------------------------
// Helpers (all base-target PTX: cp.async, ldmatrix, mma.sync)
// ---------------------------------------------------------------------------
__device__ __forceinline__ uint32_t smem_u32(const void* p) {
    uint32_t a;
    asm("{ .reg .u64 t; cvta.to.shared.u64 t, %1; cvt.u32.u64 %0, t; }"
        : "=r"(a) : "l"(p));
    return a;
}

#define SWZ(x) ((x) ^ ((((x) >> 7) & 7) << 4))   // Swizzle<3,4,3>, 128B rows

#define CPASYNC16(dst, src) \
    asm volatile("cp.async.cg.shared.global [%0], [%1], 16;" \
                 :: "r"(dst), "l"(src))
#define CPCOMMIT() asm volatile("cp.async.commit_group;" ::: "memory")
#define CPWAIT(n)  asm volatile("cp.async.wait_group %0;" :: "n"(n) : "memory")

__device__ __forceinline__ void ldsm4(uint32_t& r0, uint32_t& r1,
                                      uint32_t& r2, uint32_t& r3, uint32_t a) {
    asm volatile("ldmatrix.sync.aligned.m8n8.x4.shared.b16 {%0,%1,%2,%3}, [%4];"
                 : "=r"(r0), "=r"(r1), "=r"(r2), "=r"(r3) : "r"(a));
}

__device__ __forceinline__ void mma16816(float* d, const uint32_t* a,
                                         const uint32_t* b) {
    asm volatile(
        "mma.sync.aligned.m16n8k16.row.col.f32.f16.f16.f32 "
        "{%0,%1,%2,%3}, {%4,%5,%6,%7}, {%8,%9}, {%0,%1,%2,%3};"
        : "+f"(d[0]), "+f"(d[1]), "+f"(d[2]), "+f"(d[3])
        : "r"(a[0]), "r"(a[1]), "r"(a[2]), "r"(a[3]), "r"(b[0]), "r"(b[1]));
}

// ---------------------------------------------------------------------------
// Shared mainloop: acc += A[BMxK'] * B[BNxK']^T, both [row][k] fp16 k-major.
// 8 warps as 4(M)x2(N), warp tile 32x64, mma m16n8k16.
// ---------------------------------------------------------------------------
template <int KTOT>
__device__ __forceinline__ void gemm_mainloop(const __half* __restrict__ Ag,
                                              const __half* __restrict__ Bg,
                                              char* smem, float (&acc)[2][8][4])
{
    const int tid  = threadIdx.x;
    const int wid  = tid >> 5;
    const int lane = tid & 31;
    const int wm   = (wid & 3) * 32;
    const int wn   = (wid >> 2) * 64;
    const uint32_t sb = smem_u32(smem);
    const int KT = KTOT / BK;

    auto load_stage = [&](int kt, int s) {
        const uint32_t as = sb + s * STAGE_SZ;
        const uint32_t bs = as + STAGE_A;
        const __half* Asrc = Ag + kt * BK;
        const __half* Bsrc = Bg + kt * BK;
#pragma unroll
        for (int i = 0; i < 4; ++i) {           // A: 128 rows x 8 chunks = 1024
            const int idx = tid + i * TH;
            const int r = idx >> 3, c = idx & 7;
            CPASYNC16(as + SWZ(r * 128 + c * 16), Asrc + (size_t)r * KTOT + c * 8);
        }
#pragma unroll
        for (int i = 0; i < 4; ++i) {           // B: 128 rows x 8 chunks = 1024
            const int idx = tid + i * TH;
            const int r = idx >> 3, c = idx & 7;
            CPASYNC16(bs + SWZ(r * 128 + c * 16), Bsrc + (size_t)r * KTOT + c * 8);
        }
    };

    int fetch = 0;
    for (; fetch < STAGES - 1 && fetch < KT; ++fetch) { load_stage(fetch, fetch); CPCOMMIT(); }
    CPWAIT(STAGES - 2);
    __syncthreads();

    const int aRow = wm + (lane & 15);
    const int aCol = (lane >> 4) << 4;
    const int bRow = wn + ((lane >> 4) << 3) + (lane & 7);
    const int bCol = ((lane >> 3) & 1) << 4;

    for (int kt = 0; kt < KT; ++kt) {
        const uint32_t as = sb + (kt % STAGES) * STAGE_SZ;
        const uint32_t bs = as + STAGE_A;
#pragma unroll
        for (int ks = 0; ks < 4; ++ks) {
            uint32_t af[2][4], bf[4][4];
#pragma unroll
            for (int mi = 0; mi < 2; ++mi) {
                const uint32_t a = as + SWZ((aRow + mi * 16) * 128 + ks * 32 + aCol);
                ldsm4(af[mi][0], af[mi][1], af[mi][2], af[mi][3], a);
            }
#pragma unroll
            for (int ni = 0; ni < 4; ++ni) {
                const uint32_t a = bs + SWZ((bRow + ni * 16) * 128 + ks * 32 + bCol);
                ldsm4(bf[ni][0], bf[ni][1], bf[ni][2], bf[ni][3], a);
            }
#pragma unroll
            for (int mi = 0; mi < 2; ++mi)
#pragma unroll
                for (int ni = 0; ni < 4; ++ni) {
                    mma16816(acc[mi][ni * 2],     af[mi], &bf[ni][0]);
                    mma16816(acc[mi][ni * 2 + 1], af[mi], &bf[ni][2]);
                }
        }
        if (fetch < KT) { load_stage(fetch, fetch % STAGES); ++fetch; }
        CPCOMMIT();
        CPWAIT(STAGES - 2);
        __syncthreads();
    }
}

// ---------------------------------------------------------------------------
// QKV GEMM: g_qkv[m][n] = fp16( A1[m] . B1[n] + bias[n] )
// ---------------------------------------------------------------------------
__device__ __forceinline__ float qkv_bias(int n, const float* __restrict__ bq,
                                          const float* __restrict__ bk,
                                          const float* __restrict__ bv) {
    if (n < DD)     return bq[n];
    if (n < 2 * DD) return bk[n - DD];
    return bv[n - 2 * DD];
}

__global__ __launch_bounds__(TH, 2)
void qkv_gemm(const float* __restrict__ bq, const float* __restrict__ bk,
              const float* __restrict__ bv) {
    extern __shared__ __align__(1024) char smem[];
    const int n0 = blockIdx.x * BN;
    const int m0 = blockIdx.y * BM;

    float acc[2][8][4];
#pragma unroll
    for (int i = 0; i < 2; ++i)
#pragma unroll
        for (int j = 0; j < 8; ++j)
#pragma unroll
            for (int r = 0; r < 4; ++r) acc[i][j][r] = 0.f;

    gemm_mainloop<K1>(g_A1 + (size_t)m0 * K1, g_B1 + (size_t)n0 * K1, smem, acc);

    const int wid = threadIdx.x >> 5, lane = threadIdx.x & 31;
    const int wm = m0 + (wid & 3) * 32;
    const int wn = n0 + (wid >> 2) * 64;
#pragma unroll
    for (int mi = 0; mi < 2; ++mi) {
        const int r0 = wm + mi * 16 + (lane >> 2);
#pragma unroll
        for (int ni = 0; ni < 8; ++ni) {
            const int n = wn + ni * 8 + 2 * (lane & 3);
            const float b0 = qkv_bias(n, bq, bk, bv);
            const float b1 = qkv_bias(n + 1, bq, bk, bv);
            const __half2 v0 = __floats2half2_rn(acc[mi][ni][0] + b0, acc[mi][ni][1] + b1);
            const __half2 v1 = __floats2half2_rn(acc[mi][ni][2] + b0, acc[mi][ni][3] + b1);
            *reinterpret_cast<__half2*>(&g_qkv[(size_t)r0 * NQKV + n])       = v0;
            *reinterpret_cast<__half2*>(&g_qkv[(size_t)(r0 + 8) * NQKV + n]) = v1;
        }
    }
}

// ---------------------------------------------------------------------------
// WO GEMM: out[b][n][l] = A2[m] . B2[n] + bo[n], m = b*LL + l (transposed store)
// ---------------------------------------------------------------------------
#define CSTR 132
__global__ __launch_bounds__(TH, 2)
void wo_gemm(const float* __restrict__ bo, float* __restrict__ out) {
    extern __shared__ __align__(1024) char smem[];
    const int n0 = blockIdx.x * BN;
    const int m0 = blockIdx.y * BM;
    const int b  = m0 / LL;
    const int l0 = m0 % LL;

    float acc[2][8][4];
#pragma unroll
    for (int i = 0; i < 2; ++i)
#pragma unroll
        for (int j = 0; j < 8; ++j)
#pragma unroll
            for (int r = 0; r < 4; ++r) acc[i][j][r] = 0.f;

    gemm_mainloop<K2>(g_A2 + (size_t)m0 * K2, g_B2 + (size_t)n0 * K2, smem, acc);

    // Transpose through smem: Cs[n][m], n=128 rows, stride 132 floats (67.6KB)
    float* Cs = reinterpret_cast<float*>(smem);
    const int wid = threadIdx.x >> 5, lane = threadIdx.x & 31;
    const int wm = (wid & 3) * 32;
    const int wn = (wid >> 2) * 64;
    __syncthreads();
#pragma unroll
    for (int mi = 0; mi < 2; ++mi) {
        const int m = wm + mi * 16 + (lane >> 2);
#pragma unroll
        for (int ni = 0; ni < 8; ++ni) {
            const int n = wn + ni * 8 + 2 * (lane & 3);
            Cs[(size_t)n * CSTR + m]           = acc[mi][ni][0];
            Cs[(size_t)(n + 1) * CSTR + m]     = acc[mi][ni][1];
            Cs[(size_t)n * CSTR + m + 8]       = acc[mi][ni][2];
            Cs[(size_t)(n + 1) * CSTR + m + 8] = acc[mi][ni][3];
        }
    }
    __syncthreads();

    float* outb = out + (size_t)b * DOUT * LL;
    for (int i = threadIdx.x; i < BN * (BM / 4); i += TH) {
        const int n = i >> 5;          // 0..127
        const int c = (i & 31) * 4;    // 0..124
        const float bv = bo[n0 + n];
        float4 v;
        v.x = Cs[(size_t)n * CSTR + c + 0] + bv;
        v.y = Cs[(size_t)n * CSTR + c + 1] + bv;
        v.z = Cs[(size_t)n * CSTR + c + 2] + bv;
        v.w = Cs[(size_t)n * CSTR + c + 3] + bv;
        *reinterpret_cast<float4*>(outb + (size_t)(n0 + n) * LL + l0 + c) = v;
    }
}

// ---------------------------------------------------------------------------
// Conversions (fp32 -> fp16, with transposes)
// ---------------------------------------------------------------------------
__global__ __launch_bounds__(1024)
void conv_x_kernel(const float* __restrict__ x) {
    __shared__ float t[32][33];
    const int b  = blockIdx.z;
    const int c0 = blockIdx.y * 32, l0 = blockIdx.x * 32;
    const int tx = threadIdx.x, ty = threadIdx.y;
    t[ty][tx] = x[((size_t)(b * NHID + c0 + ty)) * LL + l0 + tx];
    __syncthreads();
    g_A1[(size_t)(b * LL + l0 + ty) * K1 + c0 + tx] = __float2half(t[tx][ty]);
}

__global__ __launch_bounds__(1024)
void conv_w_all(const float* __restrict__ Wq, const float* __restrict__ Wk,
                const float* __restrict__ Wv, const float* __restrict__ Wo) {
    __shared__ float t[32][33];
    const int bid = blockIdx.x;
    const float* W;
    __half* dst;
    int N, roff, dstride, lb, ntiles;
    if (bid < 384) {
        const int sel = bid >> 7;
        lb = bid & 127;
        W = (sel == 0) ? Wq : (sel == 1) ? Wk : Wv;
        dst = g_B1; N = DD; roff = sel * DD; dstride = K1; ntiles = DD / 32;
    } else {
        lb = bid - 384;
        W = Wo; dst = g_B2; N = DOUT; roff = 0; dstride = K2; ntiles = DOUT / 32;
    }
    const int n0 = (lb % ntiles) * 32;
    const int k0 = (lb / ntiles) * 32;
    const int tx = threadIdx.x, ty = threadIdx.y;
    t[ty][tx] = W[(size_t)(k0 + ty) * N + n0 + tx];
    __syncthreads();
    dst[(size_t)(roff + n0 + ty) * dstride + k0 + tx] = __float2half(t[tx][ty]);
}

// No-op spacer (capture slot = my launch index 3 -> qkv_gemm).
__global__ void spacer_kernel() {}

// ---------------------------------------------------------------------------
// Window-3 attention (fp16 qkv in, fp16 att out)
// ---------------------------------------------------------------------------
__global__ __launch_bounds__(256)
void attn_win3() {
    const int tid = threadIdx.x;
    const int m   = blockIdx.x * 2 + (tid >> 7);
    const int t   = tid & 127;
    const int h   = t >> 4;
    const int g   = t & 15;
    const int l   = m & (LL - 1);

    const size_t rowb = (size_t)m * NQKV;
    const int    co   = h * 64 + g * 4;

    const uint2 qraw = *reinterpret_cast<const uint2*>(g_qkv + rowb + co);
    const float2 qa = __half22float2(*reinterpret_cast<const __half2*>(&qraw.x));
    const float2 qb = __half22float2(*reinterpret_cast<const __half2*>(&qraw.y));

    float  s[3];
    float2 va[3], vb[3];
#pragma unroll
    for (int w = 0; w < 3; ++w) {
        const int lw = l + w - 1;
        float2 ka = make_float2(0.f, 0.f), kb = make_float2(0.f, 0.f);
        va[w] = make_float2(0.f, 0.f);
        vb[w] = make_float2(0.f, 0.f);
        if (lw >= 0 && lw < LL) {
            const size_t rb = rowb + (size_t)(w - 1) * NQKV;
            const uint2 kr = *reinterpret_cast<const uint2*>(g_qkv + rb + DD + co);
            const uint2 vr = *reinterpret_cast<const uint2*>(g_qkv + rb + 2 * DD + co);
            ka = __half22float2(*reinterpret_cast<const __half2*>(&kr.x));
            kb = __half22float2(*reinterpret_cast<const __half2*>(&kr.y));
            va[w] = __half22float2(*reinterpret_cast<const __half2*>(&vr.x));
            vb[w] = __half22float2(*reinterpret_cast<const __half2*>(&vr.y));
        }
        float p = qa.x * ka.x + qa.y * ka.y + qb.x * kb.x + qb.y * kb.y;
        p += __shfl_xor_sync(0xffffffffu, p, 8);
        p += __shfl_xor_sync(0xffffffffu, p, 4);
        p += __shfl_xor_sync(0xffffffffu, p, 2);
        p += __shfl_xor_sync(0xffffffffu, p, 1);
        s[w] = p * 0.125f;   // 1/sqrt(64)
    }

    const float mx = fmaxf(s[0], fmaxf(s[1], s[2]));
    const float e0 = expf(s[0] - mx), e1 = expf(s[1] - mx), e2 = expf(s[2] - mx);
    const float inv = 1.f / (e0 + e1 + e2);

    __half o[4];
    o[0] = __float2half((e0 * va[0].x + e1 * va[1].x + e2 * va[2].x) * inv);
    o[1] = __float2half((e0 * va[0].y + e1 * va[1].y + e2 * va[2].y) * inv);
    o[2] = __float2half((e0 * vb[0].x + e1 * vb[1].x + e2 * vb[2].x) * inv);
    o[3] = __float2half((e0 * vb[0].y + e1 * vb[1].y + e2 * vb[2].y) * inv);

    *reinterpret_cast<uint2*>(g_A2 + (size_t)m * K2 + co) = *reinterpret_cast<uint2*>(o);
}

// ---------------------------------------------------------------------------
extern "C" void kernel_launch(void* const* d_in, const int* in_sizes, int n_in,
                              void* d_out, int out_size)
{
    const float* x  = (const float*)d_in[0];
    const float* Wq = (const float*)d_in[1];
    const float* bq = (const float*)d_in[2];
    const float* Wk = (const float*)d_in[3];
    const float* bk = (const float*)d_in[4];
    const float* Wv = (const float*)d_in[5];
    const float* bv = (const float*)d_in[6];
    const float* Wo = (const float*)d_in[7];
    const float* bo = (const float*)d_in[8];
    float* out = (float*)d_out;

    cudaFuncSetAttribute(qkv_gemm, cudaFuncAttributeMaxDynamicSharedMemorySize, SMEM_SZ);
    cudaFuncSetAttribute(wo_gemm,  cudaFuncAttributeMaxDynamicSharedMemorySize, SMEM_SZ);

    dim3 blk(32, 32);
    // idx:   0              1           2        3 (capture)   4       5
    conv_x_kernel<<<dim3(LL / 32, NHID / 32, BB), blk>>>(x);
    conv_w_all<<<1408, blk>>>(Wq, Wk, Wv, Wo);
    spacer_kernel<<<1, 32>>>();
    qkv_gemm<<<dim3(NQKV / BN, MM / BM), TH, SMEM_SZ>>>(bq, bk, bv);
    attn_win3<<<MM / 2, 256>>>();
    wo_gemm<<<dim3(DOUT / BN, MM / BM), TH, SMEM_SZ>>>(bo, out);
}

// round 12
// speedup vs baseline: 1.1538x; 1.0002x over previous
#include <cuda_runtime.h>
#include <cuda_fp16.h>
#include <cstdint>
#include <math.h>

// ---------------------------------------------------------------------------
// Problem constants
// ---------------------------------------------------------------------------
#define BB     8
#define NHID   256
#define LL     2048
#define DD     512            // q/k/v channels
#define DOUT   2048
#define MM     (BB*LL)        // 16384
#define NQKV   1536           // q|k|v fused N
#define K1     256            // QKV GEMM K
#define K2     512            // WO GEMM K

// GEMM tiling: 128 threads = 4 warps as 2(M) x 2(N); warp tile 64x64.
// 96KB smem/CTA, 2 CTAs per SM.
#define BM     128
#define BN     128
#define BK     64
#define TH     128
#define STAGES 3
#define STAGE_A (BM*BK*2)          // 16 KB
#define STAGE_B (BN*BK*2)          // 16 KB
#define STAGE_SZ (STAGE_A+STAGE_B) // 32 KB
#define SMEM_SZ (STAGES*STAGE_SZ)  // 96 KB

// ---------------------------------------------------------------------------
// Scratch (device globals — sanctioned no-alloc path)
// ---------------------------------------------------------------------------
__device__ __half g_A1[(size_t)MM * K1];     // x^T  [m][k] fp16
__device__ __half g_B1[(size_t)NQKV * K1];   // [Wq|Wk|Wv]^T [n][k] fp16
__device__ __half g_A2[(size_t)MM * K2];     // att  [m][k] fp16
__device__ __half g_B2[(size_t)DOUT * K2];   // Wo^T [n][k] fp16
__device__ __half g_qkv[(size_t)MM * NQKV];  // fp16 q|k|v (bias included)

// ---------------------------------------------------------------------------
// Helpers (all base-target PTX: cp.async, ldmatrix, mma.sync)
// ---------------------------------------------------------------------------
__device__ __forceinline__ uint32_t smem_u32(const void* p) {
    uint32_t a;
    asm("{ .reg .u64 t; cvta.to.shared.u64 t, %1; cvt.u32.u64 %0, t; }"
        : "=r"(a) : "l"(p));
    return a;
}

#define SWZ(x) ((x) ^ ((((x) >> 7) & 7) << 4))   // Swizzle<3,4,3>, 128B rows

#define CPASYNC16(dst, src) \
    asm volatile("cp.async.cg.shared.global [%0], [%1], 16;" \
                 :: "r"(dst), "l"(src))
#define CPCOMMIT() asm volatile("cp.async.commit_group;" ::: "memory")
#define CPWAIT(n)  asm volatile("cp.async.wait_group %0;" :: "n"(n) : "memory")

__device__ __forceinline__ void ldsm4(uint32_t& r0, uint32_t& r1,
                                      uint32_t& r2, uint32_t& r3, uint32_t a) {
    asm volatile("ldmatrix.sync.aligned.m8n8.x4.shared.b16 {%0,%1,%2,%3}, [%4];"
                 : "=r"(r0), "=r"(r1), "=r"(r2), "=r"(r3) : "r"(a));
}

__device__ __forceinline__ void mma16816(float* d, const uint32_t* a,
                                         const uint32_t* b) {
    asm volatile(
        "mma.sync.aligned.m16n8k16.row.col.f32.f16.f16.f32 "
        "{%0,%1,%2,%3}, {%4,%5,%6,%7}, {%8,%9}, {%0,%1,%2,%3};"
        : "+f"(d[0]), "+f"(d[1]), "+f"(d[2]), "+f"(d[3])
        : "r"(a[0]), "r"(a[1]), "r"(a[2]), "r"(a[3]), "r"(b[0]), "r"(b[1]));
}

// ---------------------------------------------------------------------------
// Shared mainloop: acc += A[BMxK'] * B[BNxK']^T, both [row][k] fp16 k-major.
// 4 warps as 2(M)x2(N), warp tile 64x64, mma m16n8k16.
// acc[mi][j][*]: mi = m16 frag (4), j = n8 frag (8).
// ---------------------------------------------------------------------------
template <int KTOT>
__device__ __forceinline__ void gemm_mainloop(const __half* __restrict__ Ag,
                                              const __half* __restrict__ Bg,
                                              char* smem, float (&acc)[4][8][4])
{
    const int tid  = threadIdx.x;
    const int wid  = tid >> 5;
    const int lane = tid & 31;
    const int wm   = (wid & 1) * 64;
    const int wn   = (wid >> 1) * 64;
    const uint32_t sb = smem_u32(smem);
    const int KT = KTOT / BK;

    auto load_stage = [&](int kt, int s) {
        const uint32_t as = sb + s * STAGE_SZ;
        const uint32_t bs = as + STAGE_A;
        const __half* Asrc = Ag + kt * BK;
        const __half* Bsrc = Bg + kt * BK;
#pragma unroll
        for (int i = 0; i < 8; ++i) {           // A: 128 rows x 8 chunks = 1024
            const int idx = tid + i * TH;
            const int r = idx >> 3, c = idx & 7;
            CPASYNC16(as + SWZ(r * 128 + c * 16), Asrc + (size_t)r * KTOT + c * 8);
        }
#pragma unroll
        for (int i = 0; i < 8; ++i) {           // B: 128 rows x 8 chunks = 1024
            const int idx = tid + i * TH;
            const int r = idx >> 3, c = idx & 7;
            CPASYNC16(bs + SWZ(r * 128 + c * 16), Bsrc + (size_t)r * KTOT + c * 8);
        }
    };

    int fetch = 0;
    for (; fetch < STAGES - 1 && fetch < KT; ++fetch) { load_stage(fetch, fetch); CPCOMMIT(); }
    CPWAIT(STAGES - 2);
    __syncthreads();

    const int aRow = wm + (lane & 15);
    const int aCol = (lane >> 4) << 4;
    const int bRow = wn + ((lane >> 4) << 3) + (lane & 7);
    const int bCol = ((lane >> 3) & 1) << 4;

    for (int kt = 0; kt < KT; ++kt) {
        const uint32_t as = sb + (kt % STAGES) * STAGE_SZ;
        const uint32_t bs = as + STAGE_A;
#pragma unroll
        for (int ks = 0; ks < 4; ++ks) {
            uint32_t af[4][4], bf[4][4];
#pragma unroll
            for (int mi = 0; mi < 4; ++mi) {
                const uint32_t a = as + SWZ((aRow + mi * 16) * 128 + ks * 32 + aCol);
                ldsm4(af[mi][0], af[mi][1], af[mi][2], af[mi][3], a);
            }
#pragma unroll
            for (int ni = 0; ni < 4; ++ni) {
                const uint32_t a = bs + SWZ((bRow + ni * 16) * 128 + ks * 32 + bCol);
                ldsm4(bf[ni][0], bf[ni][1], bf[ni][2], bf[ni][3], a);
            }
#pragma unroll
            for (int mi = 0; mi < 4; ++mi)
#pragma unroll
                for (int ni = 0; ni < 4; ++ni) {
                    mma16816(acc[mi][ni * 2],     af[mi], &bf[ni][0]);
                    mma16816(acc[mi][ni * 2 + 1], af[mi], &bf[ni][2]);
                }
        }
        if (fetch < KT) { load_stage(fetch, fetch % STAGES); ++fetch; }
        CPCOMMIT();
        CPWAIT(STAGES - 2);
        __syncthreads();
    }
}

// ---------------------------------------------------------------------------
// QKV GEMM: g_qkv[m][n] = fp16( A1[m] . B1[n] + bias[n] )
// ---------------------------------------------------------------------------
__device__ __forceinline__ float qkv_bias(int n, const float* __restrict__ bq,
                                          const float* __restrict__ bk,
                                          const float* __restrict__ bv) {
    if (n < DD)     return bq[n];
    if (n < 2 * DD) return bk[n - DD];
    return bv[n - 2 * DD];
}

__global__ __launch_bounds__(TH, 2)
void qkv_gemm(const float* __restrict__ bq, const float* __restrict__ bk,
              const float* __restrict__ bv) {
    extern __shared__ __align__(1024) char smem[];
    const int n0 = blockIdx.x * BN;
    const int m0 = blockIdx.y * BM;

    float acc[4][8][4];
#pragma unroll
    for (int i = 0; i < 4; ++i)
#pragma unroll
        for (int j = 0; j < 8; ++j)
#pragma unroll
            for (int r = 0; r < 4; ++r) acc[i][j][r] = 0.f;

    gemm_mainloop<K1>(g_A1 + (size_t)m0 * K1, g_B1 + (size_t)n0 * K1, smem, acc);

    const int wid = threadIdx.x >> 5, lane = threadIdx.x & 31;
    const int wm = m0 + (wid & 1) * 64;
    const int wn = n0 + (wid >> 1) * 64;
#pragma unroll
    for (int mi = 0; mi < 4; ++mi) {
        const int r0 = wm + mi * 16 + (lane >> 2);
#pragma unroll
        for (int ni = 0; ni < 8; ++ni) {
            const int n = wn + ni * 8 + 2 * (lane & 3);
            const float b0 = qkv_bias(n, bq, bk, bv);
            const float b1 = qkv_bias(n + 1, bq, bk, bv);
            const __half2 v0 = __floats2half2_rn(acc[mi][ni][0] + b0, acc[mi][ni][1] + b1);
            const __half2 v1 = __floats2half2_rn(acc[mi][ni][2] + b0, acc[mi][ni][3] + b1);
            *reinterpret_cast<__half2*>(&g_qkv[(size_t)r0 * NQKV + n])       = v0;
            *reinterpret_cast<__half2*>(&g_qkv[(size_t)(r0 + 8) * NQKV + n]) = v1;
        }
    }
}

// ---------------------------------------------------------------------------
// WO GEMM: out[b][n][l] = A2[m] . B2[n] + bo[n], m = b*LL + l (transposed store)
// ---------------------------------------------------------------------------
#define CSTR 132
__global__ __launch_bounds__(TH, 2)
void wo_gemm(const float* __restrict__ bo, float* __restrict__ out) {
    extern __shared__ __align__(1024) char smem[];
    const int n0 = blockIdx.x * BN;
    const int m0 = blockIdx.y * BM;
    const int b  = m0 / LL;
    const int l0 = m0 % LL;

    float acc[4][8][4];
#pragma unroll
    for (int i = 0; i < 4; ++i)
#pragma unroll
        for (int j = 0; j < 8; ++j)
#pragma unroll
            for (int r = 0; r < 4; ++r) acc[i][j][r] = 0.f;

    gemm_mainloop<K2>(g_A2 + (size_t)m0 * K2, g_B2 + (size_t)n0 * K2, smem, acc);

    // Transpose through smem: Cs[n][m], n=128 rows, stride 132 floats (67.6KB)
    float* Cs = reinterpret_cast<float*>(smem);
    const int wid = threadIdx.x >> 5, lane = threadIdx.x & 31;
    const int wm = (wid & 1) * 64;
    const int wn = (wid >> 1) * 64;
    __syncthreads();
#pragma unroll
    for (int mi = 0; mi < 4; ++mi) {
        const int m = wm + mi * 16 + (lane >> 2);
#pragma unroll
        for (int ni = 0; ni < 8; ++ni) {
            const int n = wn + ni * 8 + 2 * (lane & 3);
            Cs[(size_t)n * CSTR + m]           = acc[mi][ni][0];
            Cs[(size_t)(n + 1) * CSTR + m]     = acc[mi][ni][1];
            Cs[(size_t)n * CSTR + m + 8]       = acc[mi][ni][2];
            Cs[(size_t)(n + 1) * CSTR + m + 8] = acc[mi][ni][3];
        }
    }
    __syncthreads();

    float* outb = out + (size_t)b * DOUT * LL;
    for (int i = threadIdx.x; i < BN * (BM / 4); i += TH) {
        const int n = i >> 5;          // 0..127
        const int c = (i & 31) * 4;    // 0..124
        const float bv = bo[n0 + n];
        float4 v;
        v.x = Cs[(size_t)n * CSTR + c + 0] + bv;
        v.y = Cs[(size_t)n * CSTR + c + 1] + bv;
        v.z = Cs[(size_t)n * CSTR + c + 2] + bv;
        v.w = Cs[(size_t)n * CSTR + c + 3] + bv;
        *reinterpret_cast<float4*>(outb + (size_t)(n0 + n) * LL + l0 + c) = v;
    }
}

// ---------------------------------------------------------------------------
// Conversions (fp32 -> fp16, with transposes)
// ---------------------------------------------------------------------------
__global__ __launch_bounds__(1024)
void conv_x_kernel(const float* __restrict__ x) {
    __shared__ float t[32][33];
    const int b  = blockIdx.z;
    const int c0 = blockIdx.y * 32, l0 = blockIdx.x * 32;
    const int tx = threadIdx.x, ty = threadIdx.y;
    t[ty][tx] = x[((size_t)(b * NHID + c0 + ty)) * LL + l0 + tx];
    __syncthreads();
    g_A1[(size_t)(b * LL + l0 + ty) * K1 + c0 + tx] = __float2half(t[tx][ty]);
}

__global__ __launch_bounds__(1024)
void conv_w_all(const float* __restrict__ Wq, const float* __restrict__ Wk,
                const float* __restrict__ Wv, const float* __restrict__ Wo) {
    __shared__ float t[32][33];
    const int bid = blockIdx.x;
    const float* W;
    __half* dst;
    int N, roff, dstride, lb, ntiles;
    if (bid < 384) {
        const int sel = bid >> 7;
        lb = bid & 127;
        W = (sel == 0) ? Wq : (sel == 1) ? Wk : Wv;
        dst = g_B1; N = DD; roff = sel * DD; dstride = K1; ntiles = DD / 32;
    } else {
        lb = bid - 384;
        W = Wo; dst = g_B2; N = DOUT; roff = 0; dstride = K2; ntiles = DOUT / 32;
    }
    const int n0 = (lb % ntiles) * 32;
    const int k0 = (lb / ntiles) * 32;
    const int tx = threadIdx.x, ty = threadIdx.y;
    t[ty][tx] = W[(size_t)(k0 + ty) * N + n0 + tx];
    __syncthreads();
    dst[(size_t)(roff + n0 + ty) * dstride + k0 + tx] = __float2half(t[tx][ty]);
}

// No-op spacer (capture slot = my launch index 3 -> qkv_gemm).
__global__ void spacer_kernel() {}

// ---------------------------------------------------------------------------
// Window-3 attention (fp16 qkv in, fp16 att out)
// ---------------------------------------------------------------------------
__global__ __launch_bounds__(256)
void attn_win3() {
    const int tid = threadIdx.x;
    const int m   = blockIdx.x * 2 + (tid >> 7);
    const int t   = tid & 127;
    const int h   = t >> 4;
    const int g   = t & 15;
    const int l   = m & (LL - 1);

    const size_t rowb = (size_t)m * NQKV;
    const int    co   = h * 64 + g * 4;

    const uint2 qraw = *reinterpret_cast<const uint2*>(g_qkv + rowb + co);
    const float2 qa = __half22float2(*reinterpret_cast<const __half2*>(&qraw.x));
    const float2 qb = __half22float2(*reinterpret_cast<const __half2*>(&qraw.y));

    float  s[3];
    float2 va[3], vb[3];
#pragma unroll
    for (int w = 0; w < 3; ++w) {
        const int lw = l + w - 1;
        float2 ka = make_float2(0.f, 0.f), kb = make_float2(0.f, 0.f);
        va[w] = make_float2(0.f, 0.f);
        vb[w] = make_float2(0.f, 0.f);
        if (lw >= 0 && lw < LL) {
            const size_t rb = rowb + (size_t)(w - 1) * NQKV;
            const uint2 kr = *reinterpret_cast<const uint2*>(g_qkv + rb + DD + co);
            const uint2 vr = *reinterpret_cast<const uint2*>(g_qkv + rb + 2 * DD + co);
            ka = __half22float2(*reinterpret_cast<const __half2*>(&kr.x));
            kb = __half22float2(*reinterpret_cast<const __half2*>(&kr.y));
            va[w] = __half22float2(*reinterpret_cast<const __half2*>(&vr.x));
            vb[w] = __half22float2(*reinterpret_cast<const __half2*>(&vr.y));
        }
        float p = qa.x * ka.x + qa.y * ka.y + qb.x * kb.x + qb.y * kb.y;
        p += __shfl_xor_sync(0xffffffffu, p, 8);
        p += __shfl_xor_sync(0xffffffffu, p, 4);
        p += __shfl_xor_sync(0xffffffffu, p, 2);
        p += __shfl_xor_sync(0xffffffffu, p, 1);
        s[w] = p * 0.125f;   // 1/sqrt(64)
    }

    const float mx = fmaxf(s[0], fmaxf(s[1], s[2]));
    const float e0 = expf(s[0] - mx), e1 = expf(s[1] - mx), e2 = expf(s[2] - mx);
    const float inv = 1.f / (e0 + e1 + e2);

    __half o[4];
    o[0] = __float2half((e0 * va[0].x + e1 * va[1].x + e2 * va[2].x) * inv);
    o[1] = __float2half((e0 * va[0].y + e1 * va[1].y + e2 * va[2].y) * inv);
    o[2] = __float2half((e0 * vb[0].x + e1 * vb[1].x + e2 * vb[2].x) * inv);
    o[3] = __float2half((e0 * vb[0].y + e1 * vb[1].y + e2 * vb[2].y) * inv);

    *reinterpret_cast<uint2*>(g_A2 + (size_t)m * K2 + co) = *reinterpret_cast<uint2*>(o);
}

// ---------------------------------------------------------------------------
extern "C" void kernel_launch(void* const* d_in, const int* in_sizes, int n_in,
                              void* d_out, int out_size)
{
    const float* x  = (const float*)d_in[0];
    const float* Wq = (const float*)d_in[1];
    const float* bq = (const float*)d_in[2];
    const float* Wk = (const float*)d_in[3];
    const float* bk = (const float*)d_in[4];
    const float* Wv = (const float*)d_in[5];
    const float* bv = (const float*)d_in[6];
    const float* Wo = (const float*)d_in[7];
    const float* bo = (const float*)d_in[8];
    float* out = (float*)d_out;

    cudaFuncSetAttribute(qkv_gemm, cudaFuncAttributeMaxDynamicSharedMemorySize, SMEM_SZ);
    cudaFuncSetAttribute(wo_gemm,  cudaFuncAttributeMaxDynamicSharedMemorySize, SMEM_SZ);

    dim3 blk(32, 32);
    // idx:   0              1           2        3 (capture)   4       5
    conv_x_kernel<<<dim3(LL / 32, NHID / 32, BB), blk>>>(x);
    conv_w_all<<<1408, blk>>>(Wq, Wk, Wv, Wo);
    spacer_kernel<<<1, 32>>>();
    qkv_gemm<<<dim3(NQKV / BN, MM / BM), TH, SMEM_SZ>>>(bq, bk, bv);
    attn_win3<<<MM / 2, 256>>>();
    wo_gemm<<<dim3(DOUT / BN, MM / BM), TH, SMEM_SZ>>>(bo, out);
}